// round 1
// baseline (speedup 1.0000x reference)
#include <cuda_runtime.h>

// Problem constants
#define EDIM   512
#define NROWS  4096      // B*L = 2*2048 (flat rows)
#define LSEQ   2048
#define CH     128       // attention chunk length
#define NC     16        // LSEQ / CH
#define NH     16        // B * n_head = 2*8
#define HD     64        // head dim

// Scratch (device globals: no allocations allowed)
__device__ float g_q[NROWS * EDIM];
__device__ float g_k[NROWS * EDIM];
__device__ float g_v[NROWS * EDIM];
__device__ float g_o[NROWS * EDIM];
__device__ float g_kv[NH * NC * HD * HD];     // per-chunk partial KV states
__device__ float g_pref[NH * NC * HD * HD];   // exclusive prefix states

// ----------------------------------------------------------------------------
// Tiled fp32 GEMM (NT): C[i][j] = act( sum_e A[i][e] * W[j][e] + bias[j] )
// A: (NROWS x 512) row-major.  W: (512 x 512) row-major (row j = output col j).
// 128x128 block tile, 256 threads, 8x8 microtile, K-tile = 16.
// ----------------------------------------------------------------------------
__device__ __forceinline__ void gemm_tile_128x128(
    const float* __restrict__ A, const float* __restrict__ W,
    const float* __restrict__ bias, float* __restrict__ C,
    int rowBase, int colBase, bool relu,
    float (*As)[132], float (*Bs)[132])
{
    const int t  = threadIdx.x;
    const int i0 = (t >> 4) * 8;
    const int j0 = (t & 15) * 8;

    float acc[8][8];
    #pragma unroll
    for (int i = 0; i < 8; i++)
        #pragma unroll
        for (int j = 0; j < 8; j++) acc[i][j] = 0.0f;

    for (int k0 = 0; k0 < EDIM; k0 += 16) {
        // Load 128x16 tiles of A and W (transposed into smem: [k][row])
        #pragma unroll
        for (int p = 0; p < 2; p++) {
            int idx = t + p * 256;          // 0..511 float4 slots
            int row = idx >> 2;             // 4 float4 per row of 16
            int kq  = (idx & 3) << 2;
            float4 av = *(const float4*)&A[(size_t)(rowBase + row) * EDIM + k0 + kq];
            As[kq + 0][row] = av.x; As[kq + 1][row] = av.y;
            As[kq + 2][row] = av.z; As[kq + 3][row] = av.w;
            float4 bv = *(const float4*)&W[(size_t)(colBase + row) * EDIM + k0 + kq];
            Bs[kq + 0][row] = bv.x; Bs[kq + 1][row] = bv.y;
            Bs[kq + 2][row] = bv.z; Bs[kq + 3][row] = bv.w;
        }
        __syncthreads();

        #pragma unroll
        for (int k = 0; k < 16; k++) {
            float a[8], b[8];
            *(float4*)&a[0] = *(const float4*)&As[k][i0];
            *(float4*)&a[4] = *(const float4*)&As[k][i0 + 4];
            *(float4*)&b[0] = *(const float4*)&Bs[k][j0];
            *(float4*)&b[4] = *(const float4*)&Bs[k][j0 + 4];
            #pragma unroll
            for (int ii = 0; ii < 8; ii++)
                #pragma unroll
                for (int jj = 0; jj < 8; jj++)
                    acc[ii][jj] = fmaf(a[ii], b[jj], acc[ii][jj]);
        }
        __syncthreads();
    }

    // Epilogue: bias (+ optional relu), float4 stores
    #pragma unroll
    for (int ii = 0; ii < 8; ii++) {
        int gr = rowBase + i0 + ii;
        float c8[8];
        #pragma unroll
        for (int jj = 0; jj < 8; jj++) {
            float cv = acc[ii][jj] + bias[colBase + j0 + jj];
            if (relu) cv = fmaxf(cv, 0.0f);
            c8[jj] = cv;
        }
        *(float4*)&C[(size_t)gr * EDIM + colBase + j0]     = *(float4*)&c8[0];
        *(float4*)&C[(size_t)gr * EDIM + colBase + j0 + 4] = *(float4*)&c8[4];
    }
}

// Fused Q/K/V projection: blockIdx.y in [0,12): y>>2 selects {q,k,v}, y&3 = col tile
__global__ void __launch_bounds__(256) qkv_gemm(
    const float* __restrict__ X,
    const float* __restrict__ Wq, const float* __restrict__ bq,
    const float* __restrict__ Wk, const float* __restrict__ bk,
    const float* __restrict__ Wv, const float* __restrict__ bv)
{
    __shared__ float As[16][132];
    __shared__ float Bs[16][132];
    int which   = blockIdx.y >> 2;
    int colBase = (blockIdx.y & 3) * 128;
    int rowBase = blockIdx.x * 128;
    if (which == 0)      gemm_tile_128x128(X, Wq, bq, g_q, rowBase, colBase, true,  As, Bs);
    else if (which == 1) gemm_tile_128x128(X, Wk, bk, g_k, rowBase, colBase, true,  As, Bs);
    else                 gemm_tile_128x128(X, Wv, bv, g_v, rowBase, colBase, false, As, Bs);
}

__global__ void __launch_bounds__(256) oproj_gemm(
    const float* __restrict__ Wo, const float* __restrict__ bo,
    float* __restrict__ out)
{
    __shared__ float As[16][132];
    __shared__ float Bs[16][132];
    gemm_tile_128x128(g_o, Wo, bo, out, blockIdx.x * 128, blockIdx.y * 128, false, As, Bs);
}

// ----------------------------------------------------------------------------
// Row L2 normalization over full E=512 for q and k (in place).
// grid (4096, 2), 128 threads; each thread owns one float4.
// ----------------------------------------------------------------------------
__global__ void __launch_bounds__(128) l2norm_rows()
{
    float* p = (blockIdx.y == 0 ? g_q : g_k) + (size_t)blockIdx.x * EDIM;
    int t = threadIdx.x;
    float4 v = ((float4*)p)[t];
    float s = v.x * v.x + v.y * v.y + v.z * v.z + v.w * v.w;
    #pragma unroll
    for (int o = 16; o > 0; o >>= 1) s += __shfl_xor_sync(0xffffffffu, s, o);
    __shared__ float red[4];
    if ((t & 31) == 0) red[t >> 5] = s;
    __syncthreads();
    float tot = red[0] + red[1] + red[2] + red[3];
    float scale = 1.0f / fmaxf(sqrtf(tot), 1e-12f);
    v.x *= scale; v.y *= scale; v.z *= scale; v.w *= scale;
    ((float4*)p)[t] = v;
}

// ----------------------------------------------------------------------------
// Pass A: per (chunk c, head n): S[d][m] = sum_{j<CH} K[c*CH+j][d] * V[c*CH+j][m]
// ----------------------------------------------------------------------------
__global__ void __launch_bounds__(256) chunk_kv()
{
    int c = blockIdx.x, n = blockIdx.y;
    int b = n >> 3, h = n & 7;
    extern __shared__ float sm[];
    float* Ks = sm;              // [128][64]
    float* Vs = sm + CH * HD;    // [128][64]
    int t = threadIdx.x;

    #pragma unroll
    for (int p = 0; p < 8; p++) {
        int idx = t + p * 256;       // 0..2047 float4 slots (128 rows x 16 f4)
        int row = idx >> 4;
        int d0  = (idx & 15) << 2;
        int l   = c * CH + row;
        size_t g = (size_t)(l * 2 + b) * EDIM + h * HD + d0;
        *(float4*)&Ks[row * HD + d0] = *(const float4*)&g_k[g];
        *(float4*)&Vs[row * HD + d0] = *(const float4*)&g_v[g];
    }
    __syncthreads();

    int d0 = (t >> 4) << 2;
    int m0 = (t & 15) << 2;
    float acc[4][4];
    #pragma unroll
    for (int i = 0; i < 4; i++)
        #pragma unroll
        for (int j = 0; j < 4; j++) acc[i][j] = 0.0f;

    for (int j = 0; j < CH; j++) {
        float4 kk = *(const float4*)&Ks[j * HD + d0];
        float4 vv = *(const float4*)&Vs[j * HD + m0];
        float ka[4] = {kk.x, kk.y, kk.z, kk.w};
        float va[4] = {vv.x, vv.y, vv.z, vv.w};
        #pragma unroll
        for (int di = 0; di < 4; di++)
            #pragma unroll
            for (int mi = 0; mi < 4; mi++)
                acc[di][mi] = fmaf(ka[di], va[mi], acc[di][mi]);
    }

    float* outp = &g_kv[((size_t)n * NC + c) * HD * HD];
    #pragma unroll
    for (int di = 0; di < 4; di++)
        *(float4*)&outp[(d0 + di) * HD + m0] = *(float4*)&acc[di][0];
}

// ----------------------------------------------------------------------------
// Pass B: exclusive prefix over chunks per head (register-carried, MLP-friendly)
// ----------------------------------------------------------------------------
__global__ void __launch_bounds__(256) prefix_kv()
{
    int n = blockIdx.x, t = threadIdx.x;
    float run[16];
    #pragma unroll
    for (int q = 0; q < 16; q++) run[q] = 0.0f;
    for (int cidx = 0; cidx < NC; cidx++) {
        #pragma unroll
        for (int q = 0; q < 16; q++) {
            int e = t + q * 256;                 // 0..4095
            size_t o = ((size_t)n * NC + cidx) * HD * HD + e;
            g_pref[o] = run[q];
            run[q] += g_kv[o];
        }
    }
}

// ----------------------------------------------------------------------------
// Pass C: per (chunk, head): out = Q @ pref + causal(Q K^T) @ V
// smem: QsT[64][132] KsT[64][132] Vs[128][64] Ps[64][64] As[128][132] = 180 KB
// ----------------------------------------------------------------------------
__global__ void __launch_bounds__(256) chunk_attn()
{
    int c = blockIdx.x, n = blockIdx.y;
    int b = n >> 3, h = n & 7;
    extern __shared__ float sm[];
    float* QsT = sm;                      // [64][132] transposed
    float* KsT = QsT + HD * 132;          // [64][132] transposed
    float* Vs  = KsT + HD * 132;          // [128][64]
    float* Ps  = Vs + CH * HD;            // [64][64]
    float* As  = Ps + HD * HD;            // [128][132]
    int t = threadIdx.x;

    #pragma unroll
    for (int p = 0; p < 8; p++) {
        int idx = t + p * 256;
        int row = idx >> 4;
        int d0  = (idx & 15) << 2;
        int l   = c * CH + row;
        size_t g = (size_t)(l * 2 + b) * EDIM + h * HD + d0;
        float4 qv = *(const float4*)&g_q[g];
        QsT[(d0 + 0) * 132 + row] = qv.x; QsT[(d0 + 1) * 132 + row] = qv.y;
        QsT[(d0 + 2) * 132 + row] = qv.z; QsT[(d0 + 3) * 132 + row] = qv.w;
        float4 kv = *(const float4*)&g_k[g];
        KsT[(d0 + 0) * 132 + row] = kv.x; KsT[(d0 + 1) * 132 + row] = kv.y;
        KsT[(d0 + 2) * 132 + row] = kv.z; KsT[(d0 + 3) * 132 + row] = kv.w;
        *(float4*)&Vs[row * HD + d0] = *(const float4*)&g_v[g];
    }
    #pragma unroll
    for (int p = 0; p < 4; p++) {
        int idx = t + p * 256;            // 1024 float4 = 4096 floats
        *(float4*)&Ps[idx * 4] =
            *(const float4*)&g_pref[((size_t)n * NC + c) * HD * HD + idx * 4];
    }
    __syncthreads();

    // A = causal-masked Q K^T  (128x128)
    {
        int i0 = (t >> 4) * 8, j0 = (t & 15) * 8;
        float acc[8][8];
        #pragma unroll
        for (int i = 0; i < 8; i++)
            #pragma unroll
            for (int j = 0; j < 8; j++) acc[i][j] = 0.0f;
        for (int d = 0; d < HD; d++) {
            float a[8], bb[8];
            *(float4*)&a[0]  = *(const float4*)&QsT[d * 132 + i0];
            *(float4*)&a[4]  = *(const float4*)&QsT[d * 132 + i0 + 4];
            *(float4*)&bb[0] = *(const float4*)&KsT[d * 132 + j0];
            *(float4*)&bb[4] = *(const float4*)&KsT[d * 132 + j0 + 4];
            #pragma unroll
            for (int ii = 0; ii < 8; ii++)
                #pragma unroll
                for (int jj = 0; jj < 8; jj++)
                    acc[ii][jj] = fmaf(a[ii], bb[jj], acc[ii][jj]);
        }
        #pragma unroll
        for (int ii = 0; ii < 8; ii++) {
            float c8[8];
            #pragma unroll
            for (int jj = 0; jj < 8; jj++)
                c8[jj] = (j0 + jj <= i0 + ii) ? acc[ii][jj] : 0.0f;
            *(float4*)&As[(i0 + ii) * 132 + j0]     = *(float4*)&c8[0];
            *(float4*)&As[(i0 + ii) * 132 + j0 + 4] = *(float4*)&c8[4];
        }
    }
    __syncthreads();

    // out = Q @ Ps  +  A @ V   (128x64)
    {
        int i0 = (t >> 4) * 8, m0 = (t & 15) * 4;
        float acc[8][4];
        #pragma unroll
        for (int i = 0; i < 8; i++)
            #pragma unroll
            for (int j = 0; j < 4; j++) acc[i][j] = 0.0f;

        for (int d = 0; d < HD; d++) {
            float a[8];
            *(float4*)&a[0] = *(const float4*)&QsT[d * 132 + i0];
            *(float4*)&a[4] = *(const float4*)&QsT[d * 132 + i0 + 4];
            float4 pv = *(const float4*)&Ps[d * HD + m0];
            float pa[4] = {pv.x, pv.y, pv.z, pv.w};
            #pragma unroll
            for (int ii = 0; ii < 8; ii++)
                #pragma unroll
                for (int mi = 0; mi < 4; mi++)
                    acc[ii][mi] = fmaf(a[ii], pa[mi], acc[ii][mi]);
        }
        for (int j = 0; j < CH; j++) {
            float4 vv = *(const float4*)&Vs[j * HD + m0];
            float va[4] = {vv.x, vv.y, vv.z, vv.w};
            #pragma unroll
            for (int ii = 0; ii < 8; ii++) {
                float aa = As[(i0 + ii) * 132 + j];
                #pragma unroll
                for (int mi = 0; mi < 4; mi++)
                    acc[ii][mi] = fmaf(aa, va[mi], acc[ii][mi]);
            }
        }
        #pragma unroll
        for (int ii = 0; ii < 8; ii++) {
            int l = c * CH + i0 + ii;
            *(float4*)&g_o[(size_t)(l * 2 + b) * EDIM + h * HD + m0] = *(float4*)&acc[ii][0];
        }
    }
}

// ----------------------------------------------------------------------------
extern "C" void kernel_launch(void* const* d_in, const int* in_sizes, int n_in,
                              void* d_out, int out_size)
{
    const float* X  = (const float*)d_in[0];
    const float* Wq = (const float*)d_in[1];
    const float* bq = (const float*)d_in[2];
    const float* Wk = (const float*)d_in[3];
    const float* bk = (const float*)d_in[4];
    const float* Wv = (const float*)d_in[5];
    const float* bv = (const float*)d_in[6];
    const float* Wo = (const float*)d_in[7];
    const float* bo = (const float*)d_in[8];
    float* out = (float*)d_out;

    (void)in_sizes; (void)n_in; (void)out_size;

    cudaFuncSetAttribute(chunk_kv,   cudaFuncAttributeMaxDynamicSharedMemorySize, 2 * CH * HD * 4);
    cudaFuncSetAttribute(chunk_attn, cudaFuncAttributeMaxDynamicSharedMemorySize,
                         (HD * 132 * 2 + CH * HD + HD * HD + CH * 132) * 4);

    qkv_gemm<<<dim3(32, 12), 256>>>(X, Wq, bq, Wk, bk, Wv, bv);
    l2norm_rows<<<dim3(4096, 2), 128>>>();
    chunk_kv<<<dim3(NC, NH), 256, 2 * CH * HD * 4>>>();
    prefix_kv<<<NH, 256>>>();
    chunk_attn<<<dim3(NC, NH), 256, (HD * 132 * 2 + CH * HD + HD * HD + CH * 132) * 4>>>();
    oproj_gemm<<<dim3(32, 4), 256>>>(Wo, bo, out);
}

// round 2
// speedup vs baseline: 2.0872x; 2.0872x over previous
#include <cuda_runtime.h>

// Problem constants
#define EDIM   512
#define NROWS  4096      // B*L = 2*2048 (flat rows)
#define LSEQ   2048
#define CH     128       // attention chunk length
#define NC     16        // LSEQ / CH
#define NH     16        // B * n_head = 2*8
#define HD     64        // head dim

// Scratch (device globals: no allocations allowed)
__device__ float g_q[NROWS * EDIM];
__device__ float g_k[NROWS * EDIM];
__device__ float g_v[NROWS * EDIM];
__device__ float g_o[NROWS * EDIM];
__device__ float g_kv[NH * NC * HD * HD];     // per-chunk partial KV states

// ----------------------------------------------------------------------------
// tf32 helpers
// ----------------------------------------------------------------------------
__device__ __forceinline__ unsigned f2tf32(float x) {
    unsigned r;
    asm("cvt.rna.tf32.f32 %0, %1;" : "=r"(r) : "f"(x));
    return r;
}

__device__ __forceinline__ void mma_tf32(float* c, const unsigned* a, const unsigned* b) {
    asm volatile(
        "mma.sync.aligned.m16n8k8.row.col.f32.tf32.tf32.f32 "
        "{%0,%1,%2,%3}, {%4,%5,%6,%7}, {%8,%9}, {%0,%1,%2,%3};"
        : "+f"(c[0]), "+f"(c[1]), "+f"(c[2]), "+f"(c[3])
        : "r"(a[0]), "r"(a[1]), "r"(a[2]), "r"(a[3]), "r"(b[0]), "r"(b[1]));
}

// ----------------------------------------------------------------------------
// tf32 tensor-core GEMM (NT): C[i][j] = act( sum_e A[i][e] * W[j][e] + bias[j] )
// Block tile 128x128, K-tile 32, 256 threads = 8 warps (2x4), warp tile 64x32,
// mma m16n8k8 grid of 4x4 per warp. Register-staged double load.
// ----------------------------------------------------------------------------
__device__ __forceinline__ void gemm_tf32_tile(
    const float* __restrict__ A, const float* __restrict__ W,
    const float* __restrict__ bias, float* __restrict__ C,
    int rowBase, int colBase, bool relu)
{
    __shared__ unsigned As[128][36];
    __shared__ unsigned Bs[128][36];

    const int t    = threadIdx.x;
    const int lane = t & 31;
    const int warp = t >> 5;
    const int wm   = (warp >> 2) * 64;   // 0 / 64
    const int wn   = (warp & 3) * 32;    // 0..96
    const int g    = lane >> 2;          // 0..7
    const int tg   = lane & 3;           // 0..3

    float acc[4][4][4];
    #pragma unroll
    for (int mt = 0; mt < 4; mt++)
        #pragma unroll
        for (int nt = 0; nt < 4; nt++)
            #pragma unroll
            for (int q = 0; q < 4; q++) acc[mt][nt][q] = 0.0f;

    // Staging registers: 4 float4 for A, 4 for B per iteration
    float4 stA[4], stB[4];

    // Prologue: load k-tile 0
    #pragma unroll
    for (int p = 0; p < 4; p++) {
        int idx = t + p * 256;            // 0..1023
        int r   = idx >> 3;               // 0..127
        int kq  = (idx & 7) << 2;         // 0..28
        stA[p] = *(const float4*)&A[(size_t)(rowBase + r) * EDIM + kq];
        stB[p] = *(const float4*)&W[(size_t)(colBase + r) * EDIM + kq];
    }
    #pragma unroll
    for (int p = 0; p < 4; p++) {
        int idx = t + p * 256;
        int r   = idx >> 3;
        int kq  = (idx & 7) << 2;
        As[r][kq + 0] = f2tf32(stA[p].x); As[r][kq + 1] = f2tf32(stA[p].y);
        As[r][kq + 2] = f2tf32(stA[p].z); As[r][kq + 3] = f2tf32(stA[p].w);
        Bs[r][kq + 0] = f2tf32(stB[p].x); Bs[r][kq + 1] = f2tf32(stB[p].y);
        Bs[r][kq + 2] = f2tf32(stB[p].z); Bs[r][kq + 3] = f2tf32(stB[p].w);
    }
    __syncthreads();

    for (int it = 0; it < EDIM / 32; it++) {
        const bool has_next = (it + 1 < EDIM / 32);
        if (has_next) {
            int k0 = (it + 1) * 32;
            #pragma unroll
            for (int p = 0; p < 4; p++) {
                int idx = t + p * 256;
                int r   = idx >> 3;
                int kq  = (idx & 7) << 2;
                stA[p] = *(const float4*)&A[(size_t)(rowBase + r) * EDIM + k0 + kq];
                stB[p] = *(const float4*)&W[(size_t)(colBase + r) * EDIM + k0 + kq];
            }
        }

        #pragma unroll
        for (int ks = 0; ks < 4; ks++) {
            const int k8 = ks * 8;
            unsigned af[4][4], bf[4][2];
            #pragma unroll
            for (int mt = 0; mt < 4; mt++) {
                int row = wm + mt * 16 + g;
                af[mt][0] = As[row][k8 + tg];
                af[mt][1] = As[row + 8][k8 + tg];
                af[mt][2] = As[row][k8 + tg + 4];
                af[mt][3] = As[row + 8][k8 + tg + 4];
            }
            #pragma unroll
            for (int nt = 0; nt < 4; nt++) {
                int nr = wn + nt * 8 + g;
                bf[nt][0] = Bs[nr][k8 + tg];
                bf[nt][1] = Bs[nr][k8 + tg + 4];
            }
            #pragma unroll
            for (int mt = 0; mt < 4; mt++)
                #pragma unroll
                for (int nt = 0; nt < 4; nt++)
                    mma_tf32(acc[mt][nt], af[mt], bf[nt]);
        }

        if (has_next) {
            __syncthreads();
            #pragma unroll
            for (int p = 0; p < 4; p++) {
                int idx = t + p * 256;
                int r   = idx >> 3;
                int kq  = (idx & 7) << 2;
                As[r][kq + 0] = f2tf32(stA[p].x); As[r][kq + 1] = f2tf32(stA[p].y);
                As[r][kq + 2] = f2tf32(stA[p].z); As[r][kq + 3] = f2tf32(stA[p].w);
                Bs[r][kq + 0] = f2tf32(stB[p].x); Bs[r][kq + 1] = f2tf32(stB[p].y);
                Bs[r][kq + 2] = f2tf32(stB[p].z); Bs[r][kq + 3] = f2tf32(stB[p].w);
            }
            __syncthreads();
        }
    }

    // Epilogue: bias + optional relu, float2 stores (cols 2tg, 2tg+1 contiguous)
    #pragma unroll
    for (int nt = 0; nt < 4; nt++) {
        int cc = colBase + wn + nt * 8 + 2 * tg;
        float bx = bias[cc], by = bias[cc + 1];
        #pragma unroll
        for (int mt = 0; mt < 4; mt++) {
            int r0 = rowBase + wm + mt * 16 + g;
            float2 v0, v1;
            v0.x = acc[mt][nt][0] + bx; v0.y = acc[mt][nt][1] + by;
            v1.x = acc[mt][nt][2] + bx; v1.y = acc[mt][nt][3] + by;
            if (relu) {
                v0.x = fmaxf(v0.x, 0.0f); v0.y = fmaxf(v0.y, 0.0f);
                v1.x = fmaxf(v1.x, 0.0f); v1.y = fmaxf(v1.y, 0.0f);
            }
            *(float2*)&C[(size_t)r0 * EDIM + cc]       = v0;
            *(float2*)&C[(size_t)(r0 + 8) * EDIM + cc] = v1;
        }
    }
}

// Fused Q/K/V projection: blockIdx.z selects matrix, (x,y) = (row,col) tiles
__global__ void __launch_bounds__(256) qkv_gemm(
    const float* __restrict__ X,
    const float* __restrict__ Wq, const float* __restrict__ bq,
    const float* __restrict__ Wk, const float* __restrict__ bk,
    const float* __restrict__ Wv, const float* __restrict__ bv)
{
    int rowBase = blockIdx.x * 128;
    int colBase = blockIdx.y * 128;
    int which   = blockIdx.z;
    if (which == 0)      gemm_tf32_tile(X, Wq, bq, g_q, rowBase, colBase, true);
    else if (which == 1) gemm_tf32_tile(X, Wk, bk, g_k, rowBase, colBase, true);
    else                 gemm_tf32_tile(X, Wv, bv, g_v, rowBase, colBase, false);
}

__global__ void __launch_bounds__(256) oproj_gemm(
    const float* __restrict__ Wo, const float* __restrict__ bo,
    float* __restrict__ out)
{
    gemm_tf32_tile(g_o, Wo, bo, out, blockIdx.x * 128, blockIdx.y * 128, false);
}

// ----------------------------------------------------------------------------
// Row L2 normalization over full E=512 for q and k (in place).
// ----------------------------------------------------------------------------
__global__ void __launch_bounds__(128) l2norm_rows()
{
    float* p = (blockIdx.y == 0 ? g_q : g_k) + (size_t)blockIdx.x * EDIM;
    int t = threadIdx.x;
    float4 v = ((float4*)p)[t];
    float s = v.x * v.x + v.y * v.y + v.z * v.z + v.w * v.w;
    #pragma unroll
    for (int o = 16; o > 0; o >>= 1) s += __shfl_xor_sync(0xffffffffu, s, o);
    __shared__ float red[4];
    if ((t & 31) == 0) red[t >> 5] = s;
    __syncthreads();
    float tot = red[0] + red[1] + red[2] + red[3];
    float scale = 1.0f / fmaxf(sqrtf(tot), 1e-12f);
    v.x *= scale; v.y *= scale; v.z *= scale; v.w *= scale;
    ((float4*)p)[t] = v;
}

// ----------------------------------------------------------------------------
// Pass A: per (chunk c, head n): S[d][m] = sum_{j<CH} K[c*CH+j][d] * V[c*CH+j][m]
// ----------------------------------------------------------------------------
__global__ void __launch_bounds__(256) chunk_kv()
{
    int c = blockIdx.x, n = blockIdx.y;
    int b = n >> 3, h = n & 7;
    extern __shared__ float sm[];
    float* Ks = sm;              // [128][64]
    float* Vs = sm + CH * HD;    // [128][64]
    int t = threadIdx.x;

    #pragma unroll
    for (int p = 0; p < 8; p++) {
        int idx = t + p * 256;       // 0..2047 float4 slots (128 rows x 16 f4)
        int row = idx >> 4;
        int d0  = (idx & 15) << 2;
        int l   = c * CH + row;
        size_t g = (size_t)(l * 2 + b) * EDIM + h * HD + d0;
        *(float4*)&Ks[row * HD + d0] = *(const float4*)&g_k[g];
        *(float4*)&Vs[row * HD + d0] = *(const float4*)&g_v[g];
    }
    __syncthreads();

    int d0 = (t >> 4) << 2;
    int m0 = (t & 15) << 2;
    float acc[4][4];
    #pragma unroll
    for (int i = 0; i < 4; i++)
        #pragma unroll
        for (int j = 0; j < 4; j++) acc[i][j] = 0.0f;

    for (int j = 0; j < CH; j++) {
        float4 kk = *(const float4*)&Ks[j * HD + d0];
        float4 vv = *(const float4*)&Vs[j * HD + m0];
        float ka[4] = {kk.x, kk.y, kk.z, kk.w};
        float va[4] = {vv.x, vv.y, vv.z, vv.w};
        #pragma unroll
        for (int di = 0; di < 4; di++)
            #pragma unroll
            for (int mi = 0; mi < 4; mi++)
                acc[di][mi] = fmaf(ka[di], va[mi], acc[di][mi]);
    }

    float* outp = &g_kv[((size_t)n * NC + c) * HD * HD];
    #pragma unroll
    for (int di = 0; di < 4; di++)
        *(float4*)&outp[(d0 + di) * HD + m0] = *(float4*)&acc[di][0];
}

// ----------------------------------------------------------------------------
// Pass C: per (chunk, head): out = Q @ (sum of prior chunk states) + causal(Q K^T) @ V
// Prefix fold: each block sums the (at most 15) preceding chunk states from L2.
// smem: QsT[64][132] KsT[64][132] Vs[128][64] Ps[64][64] As[128][132] = 180 KB
// ----------------------------------------------------------------------------
__global__ void __launch_bounds__(256) chunk_attn()
{
    int c = blockIdx.x, n = blockIdx.y;
    int b = n >> 3, h = n & 7;
    extern __shared__ float sm[];
    float* QsT = sm;                      // [64][132] transposed
    float* KsT = QsT + HD * 132;          // [64][132] transposed
    float* Vs  = KsT + HD * 132;          // [128][64]
    float* Ps  = Vs + CH * HD;            // [64][64]
    float* As  = Ps + HD * HD;            // [128][132]
    int t = threadIdx.x;

    #pragma unroll
    for (int p = 0; p < 8; p++) {
        int idx = t + p * 256;
        int row = idx >> 4;
        int d0  = (idx & 15) << 2;
        int l   = c * CH + row;
        size_t g = (size_t)(l * 2 + b) * EDIM + h * HD + d0;
        float4 qv = *(const float4*)&g_q[g];
        QsT[(d0 + 0) * 132 + row] = qv.x; QsT[(d0 + 1) * 132 + row] = qv.y;
        QsT[(d0 + 2) * 132 + row] = qv.z; QsT[(d0 + 3) * 132 + row] = qv.w;
        float4 kv = *(const float4*)&g_k[g];
        KsT[(d0 + 0) * 132 + row] = kv.x; KsT[(d0 + 1) * 132 + row] = kv.y;
        KsT[(d0 + 2) * 132 + row] = kv.z; KsT[(d0 + 3) * 132 + row] = kv.w;
        *(float4*)&Vs[row * HD + d0] = *(const float4*)&g_v[g];
    }
    // Exclusive prefix of chunk KV states, summed inline (L2-resident g_kv)
    #pragma unroll
    for (int p = 0; p < 4; p++) {
        int e4 = t + p * 256;             // float4 slot 0..1023
        float4 s = make_float4(0.0f, 0.0f, 0.0f, 0.0f);
        for (int c2 = 0; c2 < c; c2++) {
            float4 v = *(const float4*)&g_kv[((size_t)n * NC + c2) * HD * HD + e4 * 4];
            s.x += v.x; s.y += v.y; s.z += v.z; s.w += v.w;
        }
        *(float4*)&Ps[e4 * 4] = s;
    }
    __syncthreads();

    // A = causal-masked Q K^T  (128x128)
    {
        int i0 = (t >> 4) * 8, j0 = (t & 15) * 8;
        float acc[8][8];
        #pragma unroll
        for (int i = 0; i < 8; i++)
            #pragma unroll
            for (int j = 0; j < 8; j++) acc[i][j] = 0.0f;
        for (int d = 0; d < HD; d++) {
            float a[8], bb[8];
            *(float4*)&a[0]  = *(const float4*)&QsT[d * 132 + i0];
            *(float4*)&a[4]  = *(const float4*)&QsT[d * 132 + i0 + 4];
            *(float4*)&bb[0] = *(const float4*)&KsT[d * 132 + j0];
            *(float4*)&bb[4] = *(const float4*)&KsT[d * 132 + j0 + 4];
            #pragma unroll
            for (int ii = 0; ii < 8; ii++)
                #pragma unroll
                for (int jj = 0; jj < 8; jj++)
                    acc[ii][jj] = fmaf(a[ii], bb[jj], acc[ii][jj]);
        }
        #pragma unroll
        for (int ii = 0; ii < 8; ii++) {
            float c8[8];
            #pragma unroll
            for (int jj = 0; jj < 8; jj++)
                c8[jj] = (j0 + jj <= i0 + ii) ? acc[ii][jj] : 0.0f;
            *(float4*)&As[(i0 + ii) * 132 + j0]     = *(float4*)&c8[0];
            *(float4*)&As[(i0 + ii) * 132 + j0 + 4] = *(float4*)&c8[4];
        }
    }
    __syncthreads();

    // out = Q @ Ps  +  A @ V   (128x64)
    {
        int i0 = (t >> 4) * 8, m0 = (t & 15) * 4;
        float acc[8][4];
        #pragma unroll
        for (int i = 0; i < 8; i++)
            #pragma unroll
            for (int j = 0; j < 4; j++) acc[i][j] = 0.0f;

        for (int d = 0; d < HD; d++) {
            float a[8];
            *(float4*)&a[0] = *(const float4*)&QsT[d * 132 + i0];
            *(float4*)&a[4] = *(const float4*)&QsT[d * 132 + i0 + 4];
            float4 pv = *(const float4*)&Ps[d * HD + m0];
            float pa[4] = {pv.x, pv.y, pv.z, pv.w};
            #pragma unroll
            for (int ii = 0; ii < 8; ii++)
                #pragma unroll
                for (int mi = 0; mi < 4; mi++)
                    acc[ii][mi] = fmaf(a[ii], pa[mi], acc[ii][mi]);
        }
        for (int j = 0; j < CH; j++) {
            float4 vv = *(const float4*)&Vs[j * HD + m0];
            float va[4] = {vv.x, vv.y, vv.z, vv.w};
            #pragma unroll
            for (int ii = 0; ii < 8; ii++) {
                float aa = As[(i0 + ii) * 132 + j];
                #pragma unroll
                for (int mi = 0; mi < 4; mi++)
                    acc[ii][mi] = fmaf(aa, va[mi], acc[ii][mi]);
            }
        }
        #pragma unroll
        for (int ii = 0; ii < 8; ii++) {
            int l = c * CH + i0 + ii;
            *(float4*)&g_o[(size_t)(l * 2 + b) * EDIM + h * HD + m0] = *(float4*)&acc[ii][0];
        }
    }
}

// ----------------------------------------------------------------------------
extern "C" void kernel_launch(void* const* d_in, const int* in_sizes, int n_in,
                              void* d_out, int out_size)
{
    const float* X  = (const float*)d_in[0];
    const float* Wq = (const float*)d_in[1];
    const float* bq = (const float*)d_in[2];
    const float* Wk = (const float*)d_in[3];
    const float* bk = (const float*)d_in[4];
    const float* Wv = (const float*)d_in[5];
    const float* bv = (const float*)d_in[6];
    const float* Wo = (const float*)d_in[7];
    const float* bo = (const float*)d_in[8];
    float* out = (float*)d_out;

    (void)in_sizes; (void)n_in; (void)out_size;

    static bool attr_done = false;
    if (!attr_done) {
        cudaFuncSetAttribute(chunk_kv,   cudaFuncAttributeMaxDynamicSharedMemorySize, 2 * CH * HD * 4);
        cudaFuncSetAttribute(chunk_attn, cudaFuncAttributeMaxDynamicSharedMemorySize,
                             (HD * 132 * 2 + CH * HD + HD * HD + CH * 132) * 4);
        attr_done = true;
    }

    qkv_gemm<<<dim3(32, 4, 3), 256>>>(X, Wq, bq, Wk, bk, Wv, bv);
    l2norm_rows<<<dim3(4096, 2), 128>>>();
    chunk_kv<<<dim3(NC, NH), 256, 2 * CH * HD * 4>>>();
    chunk_attn<<<dim3(NC, NH), 256, (HD * 132 * 2 + CH * HD + HD * HD + CH * 132) * 4>>>();
    oproj_gemm<<<dim3(32, 4), 256>>>(Wo, bo, out);
}

// round 3
// speedup vs baseline: 2.5118x; 1.2034x over previous
#include <cuda_runtime.h>

// Problem constants
#define EDIM   512
#define NROWS  4096      // B*L = 2*2048 (flat rows)
#define LSEQ   2048
#define CH     128       // attention chunk length
#define NC     16        // LSEQ / CH
#define NH     16        // B * n_head = 2*8
#define HD     64        // head dim

// Scratch (device globals: no allocations allowed)
__device__ float g_q[NROWS * EDIM];
__device__ float g_k[NROWS * EDIM];
__device__ float g_v[NROWS * EDIM];
__device__ float g_o[NROWS * EDIM];
__device__ float g_kv[NH * NC * HD * HD];   // per-chunk KV states, stored as ST[m][d]
__device__ float g_qscale[NROWS];           // 1/max(||q_row||,1e-12)
__device__ float g_kscale[NROWS];

// ----------------------------------------------------------------------------
// tf32 helpers
// ----------------------------------------------------------------------------
__device__ __forceinline__ unsigned f2tf32(float x) {
    unsigned r;
    asm("cvt.rna.tf32.f32 %0, %1;" : "=r"(r) : "f"(x));
    return r;
}

__device__ __forceinline__ void mma_tf32(float* c, const unsigned* a, const unsigned* b) {
    asm volatile(
        "mma.sync.aligned.m16n8k8.row.col.f32.tf32.tf32.f32 "
        "{%0,%1,%2,%3}, {%4,%5,%6,%7}, {%8,%9}, {%0,%1,%2,%3};"
        : "+f"(c[0]), "+f"(c[1]), "+f"(c[2]), "+f"(c[3])
        : "r"(a[0]), "r"(a[1]), "r"(a[2]), "r"(a[3]), "r"(b[0]), "r"(b[1]));
}

// ----------------------------------------------------------------------------
// tf32 tensor-core GEMM (NT): C[i][j] = act( sum_e A[i][e] * W[j][e] + bias[j] )
// Block tile 128x128, K-tile 32, 256 threads = 8 warps (2x4), warp tile 64x32.
// ----------------------------------------------------------------------------
__device__ __forceinline__ void gemm_tf32_tile(
    const float* __restrict__ A, const float* __restrict__ W,
    const float* __restrict__ bias, float* __restrict__ C,
    int rowBase, int colBase, bool relu)
{
    __shared__ unsigned As[128][36];
    __shared__ unsigned Bs[128][36];

    const int t    = threadIdx.x;
    const int lane = t & 31;
    const int warp = t >> 5;
    const int wm   = (warp >> 2) * 64;
    const int wn   = (warp & 3) * 32;
    const int g    = lane >> 2;
    const int tg   = lane & 3;

    float acc[4][4][4];
    #pragma unroll
    for (int mt = 0; mt < 4; mt++)
        #pragma unroll
        for (int nt = 0; nt < 4; nt++)
            #pragma unroll
            for (int q = 0; q < 4; q++) acc[mt][nt][q] = 0.0f;

    float4 stA[4], stB[4];

    #pragma unroll
    for (int p = 0; p < 4; p++) {
        int idx = t + p * 256;
        int r   = idx >> 3;
        int kq  = (idx & 7) << 2;
        stA[p] = *(const float4*)&A[(size_t)(rowBase + r) * EDIM + kq];
        stB[p] = *(const float4*)&W[(size_t)(colBase + r) * EDIM + kq];
    }
    #pragma unroll
    for (int p = 0; p < 4; p++) {
        int idx = t + p * 256;
        int r   = idx >> 3;
        int kq  = (idx & 7) << 2;
        As[r][kq + 0] = f2tf32(stA[p].x); As[r][kq + 1] = f2tf32(stA[p].y);
        As[r][kq + 2] = f2tf32(stA[p].z); As[r][kq + 3] = f2tf32(stA[p].w);
        Bs[r][kq + 0] = f2tf32(stB[p].x); Bs[r][kq + 1] = f2tf32(stB[p].y);
        Bs[r][kq + 2] = f2tf32(stB[p].z); Bs[r][kq + 3] = f2tf32(stB[p].w);
    }
    __syncthreads();

    for (int it = 0; it < EDIM / 32; it++) {
        const bool has_next = (it + 1 < EDIM / 32);
        if (has_next) {
            int k0 = (it + 1) * 32;
            #pragma unroll
            for (int p = 0; p < 4; p++) {
                int idx = t + p * 256;
                int r   = idx >> 3;
                int kq  = (idx & 7) << 2;
                stA[p] = *(const float4*)&A[(size_t)(rowBase + r) * EDIM + k0 + kq];
                stB[p] = *(const float4*)&W[(size_t)(colBase + r) * EDIM + k0 + kq];
            }
        }

        #pragma unroll
        for (int ks = 0; ks < 4; ks++) {
            const int k8 = ks * 8;
            unsigned af[4][4], bf[4][2];
            #pragma unroll
            for (int mt = 0; mt < 4; mt++) {
                int row = wm + mt * 16 + g;
                af[mt][0] = As[row][k8 + tg];
                af[mt][1] = As[row + 8][k8 + tg];
                af[mt][2] = As[row][k8 + tg + 4];
                af[mt][3] = As[row + 8][k8 + tg + 4];
            }
            #pragma unroll
            for (int nt = 0; nt < 4; nt++) {
                int nr = wn + nt * 8 + g;
                bf[nt][0] = Bs[nr][k8 + tg];
                bf[nt][1] = Bs[nr][k8 + tg + 4];
            }
            #pragma unroll
            for (int mt = 0; mt < 4; mt++)
                #pragma unroll
                for (int nt = 0; nt < 4; nt++)
                    mma_tf32(acc[mt][nt], af[mt], bf[nt]);
        }

        if (has_next) {
            __syncthreads();
            #pragma unroll
            for (int p = 0; p < 4; p++) {
                int idx = t + p * 256;
                int r   = idx >> 3;
                int kq  = (idx & 7) << 2;
                As[r][kq + 0] = f2tf32(stA[p].x); As[r][kq + 1] = f2tf32(stA[p].y);
                As[r][kq + 2] = f2tf32(stA[p].z); As[r][kq + 3] = f2tf32(stA[p].w);
                Bs[r][kq + 0] = f2tf32(stB[p].x); Bs[r][kq + 1] = f2tf32(stB[p].y);
                Bs[r][kq + 2] = f2tf32(stB[p].z); Bs[r][kq + 3] = f2tf32(stB[p].w);
            }
            __syncthreads();
        }
    }

    #pragma unroll
    for (int nt = 0; nt < 4; nt++) {
        int cc = colBase + wn + nt * 8 + 2 * tg;
        float bx = bias[cc], by = bias[cc + 1];
        #pragma unroll
        for (int mt = 0; mt < 4; mt++) {
            int r0 = rowBase + wm + mt * 16 + g;
            float2 v0, v1;
            v0.x = acc[mt][nt][0] + bx; v0.y = acc[mt][nt][1] + by;
            v1.x = acc[mt][nt][2] + bx; v1.y = acc[mt][nt][3] + by;
            if (relu) {
                v0.x = fmaxf(v0.x, 0.0f); v0.y = fmaxf(v0.y, 0.0f);
                v1.x = fmaxf(v1.x, 0.0f); v1.y = fmaxf(v1.y, 0.0f);
            }
            *(float2*)&C[(size_t)r0 * EDIM + cc]       = v0;
            *(float2*)&C[(size_t)(r0 + 8) * EDIM + cc] = v1;
        }
    }
}

__global__ void __launch_bounds__(256) qkv_gemm(
    const float* __restrict__ X,
    const float* __restrict__ Wq, const float* __restrict__ bq,
    const float* __restrict__ Wk, const float* __restrict__ bk,
    const float* __restrict__ Wv, const float* __restrict__ bv)
{
    int rowBase = blockIdx.x * 128;
    int colBase = blockIdx.y * 128;
    int which   = blockIdx.z;
    if (which == 0)      gemm_tf32_tile(X, Wq, bq, g_q, rowBase, colBase, true);
    else if (which == 1) gemm_tf32_tile(X, Wk, bk, g_k, rowBase, colBase, true);
    else                 gemm_tf32_tile(X, Wv, bv, g_v, rowBase, colBase, false);
}

__global__ void __launch_bounds__(256) oproj_gemm(
    const float* __restrict__ Wo, const float* __restrict__ bo,
    float* __restrict__ out)
{
    gemm_tf32_tile(g_o, Wo, bo, out, blockIdx.x * 128, blockIdx.y * 128, false);
}

// ----------------------------------------------------------------------------
// Row sum-of-squares -> reciprocal L2 norm (read-only over q,k; writes scalars)
// ----------------------------------------------------------------------------
__global__ void __launch_bounds__(128) rowsumsq()
{
    const float* p = (blockIdx.y == 0 ? g_q : g_k) + (size_t)blockIdx.x * EDIM;
    int t = threadIdx.x;
    float4 v = ((const float4*)p)[t];
    float s = v.x * v.x + v.y * v.y + v.z * v.z + v.w * v.w;
    #pragma unroll
    for (int o = 16; o > 0; o >>= 1) s += __shfl_xor_sync(0xffffffffu, s, o);
    __shared__ float red[4];
    if ((t & 31) == 0) red[t >> 5] = s;
    __syncthreads();
    if (t == 0) {
        float tot = red[0] + red[1] + red[2] + red[3];
        float scale = 1.0f / fmaxf(sqrtf(tot), 1e-12f);
        (blockIdx.y == 0 ? g_qscale : g_kscale)[blockIdx.x] = scale;
    }
}

// ----------------------------------------------------------------------------
// Pass A (tensor): per (chunk c, head n): ST[m][d] = sum_j V[j][m] * K[j][d]
// A = Vt (64x128, row-major over j), B = Kt (row.col). 8 warps: 16x32 tiles.
// ----------------------------------------------------------------------------
__global__ void __launch_bounds__(256) chunk_kv()
{
    int c = blockIdx.x, n = blockIdx.y;
    int b = n >> 3, h = n & 7;
    extern __shared__ unsigned smu[];
    unsigned* Kt = smu;               // [64][132]
    unsigned* Vt = Kt + HD * 132;     // [64][132]
    int t = threadIdx.x;
    int lane = t & 31, w = t >> 5;
    int g = lane >> 2, tg = lane & 3;

    #pragma unroll
    for (int p = 0; p < 8; p++) {
        int idx = t + p * 256;       // 0..2047 float4 slots
        int row = idx >> 4;          // j 0..127
        int d0  = (idx & 15) << 2;
        int r   = (c * CH + row) * 2 + b;
        size_t gg = (size_t)r * EDIM + h * HD + d0;
        float sk = g_kscale[r];
        float4 kk = *(const float4*)&g_k[gg];
        Kt[(d0 + 0) * 132 + row] = f2tf32(kk.x * sk);
        Kt[(d0 + 1) * 132 + row] = f2tf32(kk.y * sk);
        Kt[(d0 + 2) * 132 + row] = f2tf32(kk.z * sk);
        Kt[(d0 + 3) * 132 + row] = f2tf32(kk.w * sk);
        float4 vv = *(const float4*)&g_v[gg];
        Vt[(d0 + 0) * 132 + row] = f2tf32(vv.x);
        Vt[(d0 + 1) * 132 + row] = f2tf32(vv.y);
        Vt[(d0 + 2) * 132 + row] = f2tf32(vv.z);
        Vt[(d0 + 3) * 132 + row] = f2tf32(vv.w);
    }
    __syncthreads();

    int m0 = (w & 3) * 16;
    int nb = (w >> 2) * 32;
    float acc[4][4];
    #pragma unroll
    for (int i = 0; i < 4; i++)
        #pragma unroll
        for (int j = 0; j < 4; j++) acc[i][j] = 0.0f;

    #pragma unroll
    for (int ks = 0; ks < 16; ks++) {
        int k8 = ks * 8;
        unsigned a[4];
        a[0] = Vt[(m0 + g) * 132 + k8 + tg];
        a[1] = Vt[(m0 + g + 8) * 132 + k8 + tg];
        a[2] = Vt[(m0 + g) * 132 + k8 + tg + 4];
        a[3] = Vt[(m0 + g + 8) * 132 + k8 + tg + 4];
        #pragma unroll
        for (int nt = 0; nt < 4; nt++) {
            unsigned bf[2];
            bf[0] = Kt[(nb + nt * 8 + g) * 132 + k8 + tg];
            bf[1] = Kt[(nb + nt * 8 + g) * 132 + k8 + tg + 4];
            mma_tf32(acc[nt], a, bf);
        }
    }

    float* outp = &g_kv[((size_t)n * NC + c) * HD * HD];
    #pragma unroll
    for (int nt = 0; nt < 4; nt++) {
        int cc = nb + nt * 8 + 2 * tg;
        *(float2*)&outp[(m0 + g) * HD + cc]     = make_float2(acc[nt][0], acc[nt][1]);
        *(float2*)&outp[(m0 + g + 8) * HD + cc] = make_float2(acc[nt][2], acc[nt][3]);
    }
}

// ----------------------------------------------------------------------------
// Pass B (tensor): per (chunk, head):
//   out = Q @ P + causal(Q K^T) @ V, all via tf32 mma.
// smem: Qs[128][68] Ks[128][68] Vt[64][132] Pt[64][68] Ss[128][132] = 184 KB
// ----------------------------------------------------------------------------
__global__ void __launch_bounds__(256) chunk_attn()
{
    int c = blockIdx.x, n = blockIdx.y;
    int b = n >> 3, h = n & 7;
    extern __shared__ unsigned smu[];
    unsigned* Qs = smu;                     // [128][68]
    unsigned* Ks = Qs + 128 * 68;           // [128][68]
    unsigned* Vt = Ks + 128 * 68;           // [64][132]
    unsigned* Pt = Vt + 64 * 132;           // [64][68]
    unsigned* Ss = Pt + 64 * 68;            // [128][132]
    int t = threadIdx.x;
    int lane = t & 31, w = t >> 5;
    int g = lane >> 2, tg = lane & 3;

    #pragma unroll
    for (int p = 0; p < 8; p++) {
        int idx = t + p * 256;
        int row = idx >> 4;
        int d0  = (idx & 15) << 2;
        int r   = (c * CH + row) * 2 + b;
        size_t gg = (size_t)r * EDIM + h * HD + d0;
        float sq = g_qscale[r];
        float sk = g_kscale[r];
        float4 qv = *(const float4*)&g_q[gg];
        Qs[row * 68 + d0 + 0] = f2tf32(qv.x * sq);
        Qs[row * 68 + d0 + 1] = f2tf32(qv.y * sq);
        Qs[row * 68 + d0 + 2] = f2tf32(qv.z * sq);
        Qs[row * 68 + d0 + 3] = f2tf32(qv.w * sq);
        float4 kk = *(const float4*)&g_k[gg];
        Ks[row * 68 + d0 + 0] = f2tf32(kk.x * sk);
        Ks[row * 68 + d0 + 1] = f2tf32(kk.y * sk);
        Ks[row * 68 + d0 + 2] = f2tf32(kk.z * sk);
        Ks[row * 68 + d0 + 3] = f2tf32(kk.w * sk);
        float4 vv = *(const float4*)&g_v[gg];
        Vt[(d0 + 0) * 132 + row] = f2tf32(vv.x);
        Vt[(d0 + 1) * 132 + row] = f2tf32(vv.y);
        Vt[(d0 + 2) * 132 + row] = f2tf32(vv.z);
        Vt[(d0 + 3) * 132 + row] = f2tf32(vv.w);
    }
    // Exclusive prefix over prior chunk states (fp32 accumulate, tf32 store)
    #pragma unroll
    for (int p = 0; p < 4; p++) {
        int slot = t + p * 256;               // 0..1023 float4 slots
        int m  = slot >> 4;
        int d0 = (slot & 15) << 2;
        float4 s = make_float4(0.0f, 0.0f, 0.0f, 0.0f);
        for (int c2 = 0; c2 < c; c2++) {
            float4 v = *(const float4*)&g_kv[((size_t)n * NC + c2) * HD * HD + m * HD + d0];
            s.x += v.x; s.y += v.y; s.z += v.z; s.w += v.w;
        }
        Pt[m * 68 + d0 + 0] = f2tf32(s.x);
        Pt[m * 68 + d0 + 1] = f2tf32(s.y);
        Pt[m * 68 + d0 + 2] = f2tf32(s.z);
        Pt[m * 68 + d0 + 3] = f2tf32(s.w);
    }
    __syncthreads();

    const int i0 = w * 16;
    const int r0 = i0 + g, r1 = i0 + g + 8;

    // Pass 1: S = Q K^T (128x128, k=64), causal mask, tf32 into Ss
    {
        float acc1[16][4];
        #pragma unroll
        for (int nt = 0; nt < 16; nt++)
            #pragma unroll
            for (int q = 0; q < 4; q++) acc1[nt][q] = 0.0f;

        #pragma unroll
        for (int ks = 0; ks < 8; ks++) {
            int k8 = ks * 8;
            unsigned a[4];
            a[0] = Qs[r0 * 68 + k8 + tg];
            a[1] = Qs[r1 * 68 + k8 + tg];
            a[2] = Qs[r0 * 68 + k8 + tg + 4];
            a[3] = Qs[r1 * 68 + k8 + tg + 4];
            #pragma unroll
            for (int nt = 0; nt < 16; nt++) {
                unsigned bf[2];
                bf[0] = Ks[(nt * 8 + g) * 68 + k8 + tg];
                bf[1] = Ks[(nt * 8 + g) * 68 + k8 + tg + 4];
                mma_tf32(acc1[nt], a, bf);
            }
        }
        #pragma unroll
        for (int nt = 0; nt < 16; nt++) {
            int j0 = nt * 8 + 2 * tg;
            Ss[r0 * 132 + j0]     = f2tf32(j0     <= r0 ? acc1[nt][0] : 0.0f);
            Ss[r0 * 132 + j0 + 1] = f2tf32(j0 + 1 <= r0 ? acc1[nt][1] : 0.0f);
            Ss[r1 * 132 + j0]     = f2tf32(j0     <= r1 ? acc1[nt][2] : 0.0f);
            Ss[r1 * 132 + j0 + 1] = f2tf32(j0 + 1 <= r1 ? acc1[nt][3] : 0.0f);
        }
    }
    __syncwarp();   // Ss rows of this warp written by this warp's lanes only

    // Pass 2: out = Q @ Pt + Ss @ Vt  (128x64)
    {
        float acc2[8][4];
        #pragma unroll
        for (int nt = 0; nt < 8; nt++)
            #pragma unroll
            for (int q = 0; q < 4; q++) acc2[nt][q] = 0.0f;

        #pragma unroll
        for (int ks = 0; ks < 8; ks++) {            // Q @ P, k = 64
            int k8 = ks * 8;
            unsigned a[4];
            a[0] = Qs[r0 * 68 + k8 + tg];
            a[1] = Qs[r1 * 68 + k8 + tg];
            a[2] = Qs[r0 * 68 + k8 + tg + 4];
            a[3] = Qs[r1 * 68 + k8 + tg + 4];
            #pragma unroll
            for (int nt = 0; nt < 8; nt++) {
                unsigned bf[2];
                bf[0] = Pt[(nt * 8 + g) * 68 + k8 + tg];
                bf[1] = Pt[(nt * 8 + g) * 68 + k8 + tg + 4];
                mma_tf32(acc2[nt], a, bf);
            }
        }
        #pragma unroll
        for (int ks = 0; ks < 16; ks++) {           // S @ V, k = 128
            int k8 = ks * 8;
            unsigned a[4];
            a[0] = Ss[r0 * 132 + k8 + tg];
            a[1] = Ss[r1 * 132 + k8 + tg];
            a[2] = Ss[r0 * 132 + k8 + tg + 4];
            a[3] = Ss[r1 * 132 + k8 + tg + 4];
            #pragma unroll
            for (int nt = 0; nt < 8; nt++) {
                unsigned bf[2];
                bf[0] = Vt[(nt * 8 + g) * 132 + k8 + tg];
                bf[1] = Vt[(nt * 8 + g) * 132 + k8 + tg + 4];
                mma_tf32(acc2[nt], a, bf);
            }
        }

        #pragma unroll
        for (int nt = 0; nt < 8; nt++) {
            int cc = nt * 8 + 2 * tg;
            int l0 = (c * CH + r0) * 2 + b;
            int l1 = (c * CH + r1) * 2 + b;
            *(float2*)&g_o[(size_t)l0 * EDIM + h * HD + cc] = make_float2(acc2[nt][0], acc2[nt][1]);
            *(float2*)&g_o[(size_t)l1 * EDIM + h * HD + cc] = make_float2(acc2[nt][2], acc2[nt][3]);
        }
    }
}

// ----------------------------------------------------------------------------
#define CHUNK_KV_SMEM   (2 * HD * 132 * 4)
#define CHUNK_ATTN_SMEM ((128 * 68 * 2 + 64 * 132 + 64 * 68 + 128 * 132) * 4)

extern "C" void kernel_launch(void* const* d_in, const int* in_sizes, int n_in,
                              void* d_out, int out_size)
{
    const float* X  = (const float*)d_in[0];
    const float* Wq = (const float*)d_in[1];
    const float* bq = (const float*)d_in[2];
    const float* Wk = (const float*)d_in[3];
    const float* bk = (const float*)d_in[4];
    const float* Wv = (const float*)d_in[5];
    const float* bv = (const float*)d_in[6];
    const float* Wo = (const float*)d_in[7];
    const float* bo = (const float*)d_in[8];
    float* out = (float*)d_out;

    (void)in_sizes; (void)n_in; (void)out_size;

    cudaFuncSetAttribute(chunk_kv,   cudaFuncAttributeMaxDynamicSharedMemorySize, CHUNK_KV_SMEM);
    cudaFuncSetAttribute(chunk_attn, cudaFuncAttributeMaxDynamicSharedMemorySize, CHUNK_ATTN_SMEM);

    qkv_gemm<<<dim3(32, 4, 3), 256>>>(X, Wq, bq, Wk, bk, Wv, bv);
    rowsumsq<<<dim3(4096, 2), 128>>>();
    chunk_kv<<<dim3(NC, NH), 256, CHUNK_KV_SMEM>>>();
    chunk_attn<<<dim3(NC, NH), 256, CHUNK_ATTN_SMEM>>>();
    oproj_gemm<<<dim3(32, 4), 256>>>(Wo, bo, out);
}